// round 3
// baseline (speedup 1.0000x reference)
#include <cuda_runtime.h>

// FactorizedTrilinear: B=4, Z=X=C=128, D=V=2, IN=512, R=256
// Stage 1 (proj_kernel): p_k[b,z,d,v,r] = x_k[b,z,d,v,:] @ W_k + b_k
//   stored transposed as P_k[b][r][row][dv]  (row = z/x/c, dv = d*2+v)
// Stage 2 (tri_kernel):  out[b,z,x,c,d,v] = sum_r P1[b][r][z][dv]*P2[b][r][x][dv]*P3[b][r][c][dv]

#define NB  4
#define NZ  128
#define NIN 512
#define NR  256
#define NDV 4

// Scratch: 3 x 2MB fp32, static device arrays (no allocations allowed).
__device__ __align__(16) float g_P1[NB * NR * NZ * NDV];
__device__ __align__(16) float g_P2[NB * NR * NZ * NDV];
__device__ __align__(16) float g_P3[NB * NR * NZ * NDV];

// ---------------------------------------------------------------------------
// Projection: grid (z=128, b=4, k=3), 256 threads.
// Each block handles one (b,z) row-group (4 dv rows of IN=512) for tensor k.
// Thread t computes r = t for all 4 dv, writes one float4 to P_k[b][t][z][0..3].
// ---------------------------------------------------------------------------
__global__ __launch_bounds__(256) void proj_kernel(
    const float* __restrict__ x1, const float* __restrict__ x2, const float* __restrict__ x3,
    const float* __restrict__ W1, const float* __restrict__ bb1,
    const float* __restrict__ W2, const float* __restrict__ bb2,
    const float* __restrict__ W3, const float* __restrict__ bb3)
{
    __shared__ __align__(16) float xs[NDV * NIN];   // 8 KB: 4 dv rows of x
    __shared__ __align__(16) float ws[32 * NR];     // 32 KB: W chunk [32][256]

    const int z = blockIdx.x;
    const int b = blockIdx.y;
    const int k = blockIdx.z;

    const float* x  = (k == 0) ? x1  : (k == 1) ? x2  : x3;
    const float* W  = (k == 0) ? W1  : (k == 1) ? W2  : W3;
    const float* bs = (k == 0) ? bb1 : (k == 1) ? bb2 : bb3;
    float*       P  = (k == 0) ? g_P1 : (k == 1) ? g_P2 : g_P3;

    const int tid = threadIdx.x;

    // Load the 4 dv rows of x for (b,z): 2048 floats = 512 float4, coalesced.
    const float4* xg = (const float4*)(x + (size_t)(b * NZ + z) * NDV * NIN);
    float4* xs4 = (float4*)xs;
#pragma unroll
    for (int i = 0; i < 2; i++) xs4[tid + i * 256] = xg[tid + i * 256];

    float a0 = bs[tid];
    float a1 = a0, a2 = a0, a3 = a0;

    for (int ic = 0; ic < NIN / 32; ic++) {
        __syncthreads();  // protect ws reuse (also covers xs before first use)
        // Load W chunk: rows [ic*32, ic*32+32) x 256, 8192 floats = 2048 float4.
        const float4* wg = (const float4*)(W + ic * 32 * NR);
        float4* ws4 = (float4*)ws;
#pragma unroll
        for (int i = 0; i < 8; i++) ws4[tid + i * 256] = wg[tid + i * 256];
        __syncthreads();

#pragma unroll
        for (int i4 = 0; i4 < 8; i4++) {
            float4 xv0 = xs4[(0 * NIN + ic * 32) / 4 + i4];
            float4 xv1 = xs4[(1 * NIN + ic * 32) / 4 + i4];
            float4 xv2 = xs4[(2 * NIN + ic * 32) / 4 + i4];
            float4 xv3 = xs4[(3 * NIN + ic * 32) / 4 + i4];
            const float* p0 = (const float*)&xv0;
            const float* p1 = (const float*)&xv1;
            const float* p2 = (const float*)&xv2;
            const float* p3 = (const float*)&xv3;
#pragma unroll
            for (int ii = 0; ii < 4; ii++) {
                float w = ws[(i4 * 4 + ii) * NR + tid];   // conflict-free: lanes contiguous
                a0 = fmaf(p0[ii], w, a0);
                a1 = fmaf(p1[ii], w, a1);
                a2 = fmaf(p2[ii], w, a2);
                a3 = fmaf(p3[ii], w, a3);
            }
        }
    }

    float4 o;
    o.x = a0; o.y = a1; o.z = a2; o.w = a3;
    *(float4*)(P + ((size_t)(b * NR + tid) * NZ + z) * NDV) = o;
}

// ---------------------------------------------------------------------------
// Trilinear: grid 2048 = b(4) * zt(8) * xt(8) * ct(8), 256 threads.
// Block tile: 16z x 16x x 16c x 4dv. Thread tile: 2z x 2x x 4c x 4dv = 64 accs.
// Smem per r-chunk (32 r): row of [16z*4dv | 16x*4dv | 16c*4dv] = 192 floats.
// Inner loop per r: 8 LDS.128 (mostly broadcast) + 16 MUL + 64 FFMA.
// ---------------------------------------------------------------------------
__global__ __launch_bounds__(256, 2) void tri_kernel(float* __restrict__ out)
{
    __shared__ __align__(16) float S[32 * 192];   // 24 KB

    const int bid = blockIdx.x;
    const int ct  = bid & 7;
    const int xt  = (bid >> 3) & 7;
    const int zt  = (bid >> 6) & 7;
    const int b   = bid >> 9;
    const int z0 = zt * 16, x0 = xt * 16, c0 = ct * 16;

    const int tid = threadIdx.x;
    const int cp = tid & 3;          // 4 c-quads
    const int xp = (tid >> 2) & 7;   // 8 x-pairs
    const int zp = tid >> 5;         // 8 z-pairs (uniform per warp -> broadcast LDS)

    float acc[2][2][4][4];
#pragma unroll
    for (int i = 0; i < 2; i++)
#pragma unroll
        for (int j = 0; j < 2; j++)
#pragma unroll
            for (int kk = 0; kk < 4; kk++)
#pragma unroll
                for (int dv = 0; dv < 4; dv++) acc[i][j][kk][dv] = 0.0f;

    const float4* P1g = (const float4*)g_P1;   // indexed [(b*NR+r)*NZ + row]
    const float4* P2g = (const float4*)g_P2;
    const float4* P3g = (const float4*)g_P3;
    float4* S4 = (float4*)S;                   // row stride = 48 float4

    for (int ec = 0; ec < NR; ec += 32) {
        __syncthreads();
        {
            const int e = tid >> 4;       // 0..15
            const int q = tid & 15;       // 0..15 float4 within a 64-float region
#pragma unroll
            for (int s = 0; s < 2; s++) {
                const int ee = e + s * 16;                 // 0..31
                const size_t gro = (size_t)(b * NR + ec + ee) * NZ;
                S4[ee * 48 +      q] = P1g[gro + z0 + q];  // z region
                S4[ee * 48 + 16 + q] = P2g[gro + x0 + q];  // x region
                S4[ee * 48 + 32 + q] = P3g[gro + c0 + q];  // c region
            }
        }
        __syncthreads();

#pragma unroll 4
        for (int e = 0; e < 32; e++) {
            const float* row = S + e * 192;
            float4 rz0 = *(const float4*)(row + (2 * zp + 0) * 4);
            float4 rz1 = *(const float4*)(row + (2 * zp + 1) * 4);
            float4 rx0 = *(const float4*)(row + 64 + (2 * xp + 0) * 4);
            float4 rx1 = *(const float4*)(row + 64 + (2 * xp + 1) * 4);
            float4 rc[4];
#pragma unroll
            for (int kk = 0; kk < 4; kk++)
                rc[kk] = *(const float4*)(row + 128 + (4 * cp + kk) * 4);

            const float* pz0 = (const float*)&rz0;
            const float* pz1 = (const float*)&rz1;
            const float* px0 = (const float*)&rx0;
            const float* px1 = (const float*)&rx1;

#pragma unroll
            for (int i = 0; i < 2; i++) {
                const float* pz = i ? pz1 : pz0;
#pragma unroll
                for (int j = 0; j < 2; j++) {
                    const float* px = j ? px1 : px0;
#pragma unroll
                    for (int dv = 0; dv < 4; dv++) {
                        float t = pz[dv] * px[dv];
#pragma unroll
                        for (int kk = 0; kk < 4; kk++)
                            acc[i][j][kk][dv] =
                                fmaf(t, ((const float*)&rc[kk])[dv], acc[i][j][kk][dv]);
                    }
                }
            }
        }
    }

    // Store: per (i,j), 16 contiguous floats (4c x 4dv) = 4 float4, coalesced
    // across cp lanes (4 lanes cover 256B contiguous).
#pragma unroll
    for (int i = 0; i < 2; i++) {
#pragma unroll
        for (int j = 0; j < 2; j++) {
            const int zz = z0 + 2 * zp + i;
            const int xx = x0 + 2 * xp + j;
            float4* og = (float4*)(out +
                ((((size_t)b * NZ + zz) * NZ + xx) * NZ + (c0 + 4 * cp)) * NDV);
#pragma unroll
            for (int kk = 0; kk < 4; kk++) {
                float4 o;
                o.x = acc[i][j][kk][0];
                o.y = acc[i][j][kk][1];
                o.z = acc[i][j][kk][2];
                o.w = acc[i][j][kk][3];
                og[kk] = o;
            }
        }
    }
}

// ---------------------------------------------------------------------------
extern "C" void kernel_launch(void* const* d_in, const int* in_sizes, int n_in,
                              void* d_out, int out_size)
{
    (void)in_sizes; (void)n_in; (void)out_size;
    const float* x1 = (const float*)d_in[0];
    const float* x2 = (const float*)d_in[1];
    const float* x3 = (const float*)d_in[2];
    const float* W1 = (const float*)d_in[3];
    const float* b1 = (const float*)d_in[4];
    const float* W2 = (const float*)d_in[5];
    const float* b2 = (const float*)d_in[6];
    const float* W3 = (const float*)d_in[7];
    const float* b3 = (const float*)d_in[8];
    float* out = (float*)d_out;

    proj_kernel<<<dim3(NZ, NB, 3), 256>>>(x1, x2, x3, W1, b1, W2, b2, W3, b3);
    tri_kernel<<<2048, 256>>>(out);
}

// round 5
// speedup vs baseline: 1.6188x; 1.6188x over previous
#include <cuda_runtime.h>
#include <cstdint>

// FactorizedTrilinear: B=4, Z=X=C=128, D=V=2 (dv=4), IN=512, R=256
// Stage 1 (proj_kernel, fp32 SIMT): P_k[b][dv][row][e] = x_k[b,row,dv,:] @ W_k + b_k
// Stage 2 (tri_mma_kernel, mma.sync m16n8k8 tf32):
//   out[b,z,x,c,dv] = sum_e (p1[z,e]*p2[x,e]) * p3[c,e]
//   A[(4z x 32x), e] = tf32(p1*p2)  (row-major), B[c, e] = tf32(p3) (B col-major k x n)

#define NB  4
#define NZ  128
#define NIN 512
#define NR  256   // e (K dim)
#define NDV 4

// P scratch: [ (b*4+dv)*128 + row ] * 256 + e   (2 MB each)
__device__ __align__(16) float g_P1[NB * NDV * NZ * NR];
__device__ __align__(16) float g_P2[NB * NDV * NZ * NR];
__device__ __align__(16) float g_P3[NB * NDV * NZ * NR];

__device__ __forceinline__ uint32_t f2tf32(float f) {
    uint32_t u;
    asm("cvt.rna.tf32.f32 %0, %1;" : "=r"(u) : "f"(f));
    return u;
}

// ---------------------------------------------------------------------------
// Projection: grid (32, 4, 3), 256 threads. Block = 4 z rows (16 dv-rows),
// all 256 r (r = tid). W streamed in 16-e chunks.
// ---------------------------------------------------------------------------
__global__ __launch_bounds__(256) void proj_kernel(
    const float* __restrict__ x1, const float* __restrict__ x2, const float* __restrict__ x3,
    const float* __restrict__ W1, const float* __restrict__ bb1,
    const float* __restrict__ W2, const float* __restrict__ bb2,
    const float* __restrict__ W3, const float* __restrict__ bb3)
{
    __shared__ __align__(16) float xs[4 * NIN * NDV];  // [z][e][dv] 32 KB
    __shared__ __align__(16) float ws[16 * NR];        // [e16][r]   16 KB

    const int z0 = blockIdx.x * 4;
    const int b  = blockIdx.y;
    const int k  = blockIdx.z;

    const float* x  = (k == 0) ? x1  : (k == 1) ? x2  : x3;
    const float* W  = (k == 0) ? W1  : (k == 1) ? W2  : W3;
    const float* bs = (k == 0) ? bb1 : (k == 1) ? bb2 : bb3;
    float*       P  = (k == 0) ? g_P1 : (k == 1) ? g_P2 : g_P3;

    const int tid = threadIdx.x;

    const float* xg = x + ((size_t)(b * NZ + z0)) * NDV * NIN;
#pragma unroll
    for (int i = 0; i < 32; i++) {
        int idx = i * 256 + tid;
        int e   = idx & (NIN - 1);
        int zdv = idx >> 9;                 // 0..15 = z*4+dv
        xs[((zdv >> 2) * NIN + e) * NDV + (zdv & 3)] = xg[zdv * NIN + e];
    }

    float acc[4][NDV];
    {
        float bv = bs[tid];
#pragma unroll
        for (int z = 0; z < 4; z++)
#pragma unroll
            for (int dv = 0; dv < NDV; dv++) acc[z][dv] = bv;
    }

    for (int ec = 0; ec < NIN / 16; ec++) {
        __syncthreads();
        const float4* wg = (const float4*)(W + ec * 16 * NR);
        float4* ws4 = (float4*)ws;
#pragma unroll
        for (int i = 0; i < 4; i++) ws4[i * 256 + tid] = wg[i * 256 + tid];
        __syncthreads();

#pragma unroll
        for (int e16 = 0; e16 < 16; e16++) {
            float w = ws[e16 * NR + tid];
            int e = ec * 16 + e16;
#pragma unroll
            for (int z = 0; z < 4; z++) {
                float4 xv = *(const float4*)&xs[(z * NIN + e) * NDV];
                acc[z][0] = fmaf(xv.x, w, acc[z][0]);
                acc[z][1] = fmaf(xv.y, w, acc[z][1]);
                acc[z][2] = fmaf(xv.z, w, acc[z][2]);
                acc[z][3] = fmaf(xv.w, w, acc[z][3]);
            }
        }
    }

#pragma unroll
    for (int z = 0; z < 4; z++)
#pragma unroll
        for (int dv = 0; dv < NDV; dv++)
            P[((size_t)((b * NDV + dv) * NZ + z0 + z)) * NR + tid] = acc[z][dv];
}

// ---------------------------------------------------------------------------
// Trilinear via mma.sync.aligned.m16n8k8 tf32.
// Grid (32, 8, 4): zq(32) x [xq(4)|ch(2)] x b(4). CTA: M=128 rows=(4z x 32x),
// N=64 c, dv loop x K(256 in 8 chunks of 32). 8 warps = 8 M16 tiles; each
// warp: 8 n-tiles x 4 k-steps per chunk. 32 fp32 accumulators per thread.
// ---------------------------------------------------------------------------
#define KC 32
#define APAD 36   // 32 + 4 pad (floats per row)

__global__ __launch_bounds__(256) void tri_mma_kernel(float* __restrict__ out)
{
    __shared__ uint32_t As[128 * APAD];   // 18 KB, tf32 A tile [m][k]
    __shared__ uint32_t Bs[64 * APAD];    //  9 KB, tf32 B tile [n(c)][k]
    __shared__ float    p1s[4 * KC];      // 512 B

    const int tid  = threadIdx.x;
    const int wid  = tid >> 5;
    const int lane = tid & 31;
    const int grp  = lane >> 2;   // 0..7
    const int thr4 = lane & 3;    // 0..3

    const int zq = blockIdx.x;            // z0 = zq*4
    const int xq = blockIdx.y & 3;        // x0 = xq*32
    const int ch = blockIdx.y >> 2;       // c0 = ch*64
    const int b  = blockIdx.z;
    const int wm = wid * 16;              // warp M offset in CTA tile

    for (int dv = 0; dv < NDV; dv++) {
        const float* p1b = g_P1 + ((size_t)((b * NDV + dv) * NZ + zq * 4)) * NR;
        const float* p2b = g_P2 + ((size_t)((b * NDV + dv) * NZ + xq * 32)) * NR;
        const float* p3b = g_P3 + ((size_t)((b * NDV + dv) * NZ + ch * 64)) * NR;

        float d[8][4];
#pragma unroll
        for (int nt = 0; nt < 8; nt++)
#pragma unroll
            for (int i = 0; i < 4; i++) d[nt][i] = 0.0f;

        for (int ck = 0; ck < NR / KC; ck++) {
            __syncthreads();   // previous chunk's MMA reads done
            // stage p1 chunk: 4z x 32k
            if (tid < 128)
                p1s[tid] = p1b[(tid >> 5) * NR + ck * KC + (tid & 31)];
            __syncthreads();   // p1s visible for A build

            // Build A: each thread reads one p2 value, writes 4 rows (zl 0..3).
#pragma unroll
            for (int i = 0; i < 4; i++) {
                int g  = i * 256 + tid;      // 0..1023
                int xl = g >> 5;             // 0..31
                int kk = g & 31;
                float p2v = p2b[xl * NR + ck * KC + kk];
#pragma unroll
                for (int zl = 0; zl < 4; zl++)
                    As[(zl * 32 + xl) * APAD + kk] =
                        f2tf32(p1s[zl * KC + kk] * p2v);
            }
            // Build B: 64c x 32k
#pragma unroll
            for (int i = 0; i < 8; i++) {
                int g = i * 256 + tid;       // 0..2047
                int c = g >> 5;
                int kk = g & 31;
                Bs[c * APAD + kk] = f2tf32(p3b[c * NR + ck * KC + kk]);
            }
            __syncthreads();

            // MMA: 4 k-steps of 8
#pragma unroll
            for (int s = 0; s < 4; s++) {
                const int k0 = s * 8;
                uint32_t a0 = As[(wm + grp)     * APAD + k0 + thr4];
                uint32_t a1 = As[(wm + grp + 8) * APAD + k0 + thr4];
                uint32_t a2 = As[(wm + grp)     * APAD + k0 + thr4 + 4];
                uint32_t a3 = As[(wm + grp + 8) * APAD + k0 + thr4 + 4];
#pragma unroll
                for (int nt = 0; nt < 8; nt++) {
                    uint32_t b0 = Bs[(nt * 8 + grp) * APAD + k0 + thr4];
                    uint32_t b1 = Bs[(nt * 8 + grp) * APAD + k0 + thr4 + 4];
                    asm volatile(
                        "mma.sync.aligned.m16n8k8.row.col.f32.tf32.tf32.f32 "
                        "{%0,%1,%2,%3}, {%4,%5,%6,%7}, {%8,%9}, {%0,%1,%2,%3};"
                        : "+f"(d[nt][0]), "+f"(d[nt][1]),
                          "+f"(d[nt][2]), "+f"(d[nt][3])
                        : "r"(a0), "r"(a1), "r"(a2), "r"(a3),
                          "r"(b0), "r"(b1));
                }
            }
        }

        // Epilogue for this dv. D row r -> (z,x): m = wm + r (+8), zl=m>>5, xl=m&31.
        {
            const int m0 = wm + grp;
            const int m1 = m0 + 8;
            const int z0g = zq * 4, x0g = xq * 32;
            const size_t rb0 = ((((size_t)(b * NZ + z0g + (m0 >> 5))) * NZ
                                 + x0g + (m0 & 31)) * NZ) * NDV + dv;
            const size_t rb1 = ((((size_t)(b * NZ + z0g + (m1 >> 5))) * NZ
                                 + x0g + (m1 & 31)) * NZ) * NDV + dv;
#pragma unroll
            for (int nt = 0; nt < 8; nt++) {
                const int cg = ch * 64 + nt * 8 + thr4 * 2;
                out[rb0 + (size_t)cg * NDV]       = d[nt][0];
                out[rb0 + (size_t)(cg + 1) * NDV] = d[nt][1];
                out[rb1 + (size_t)cg * NDV]       = d[nt][2];
                out[rb1 + (size_t)(cg + 1) * NDV] = d[nt][3];
            }
        }
        __syncthreads();  // all warps done with smem before next dv restage
    }
}

// ---------------------------------------------------------------------------
extern "C" void kernel_launch(void* const* d_in, const int* in_sizes, int n_in,
                              void* d_out, int out_size)
{
    (void)in_sizes; (void)n_in; (void)out_size;
    const float* x1 = (const float*)d_in[0];
    const float* x2 = (const float*)d_in[1];
    const float* x3 = (const float*)d_in[2];
    const float* W1 = (const float*)d_in[3];
    const float* b1 = (const float*)d_in[4];
    const float* W2 = (const float*)d_in[5];
    const float* b2 = (const float*)d_in[6];
    const float* W3 = (const float*)d_in[7];
    const float* b3 = (const float*)d_in[8];
    float* out = (float*)d_out;

    proj_kernel<<<dim3(32, NB, 3), 256>>>(x1, x2, x3, W1, b1, W2, b2, W3, b3);
    tri_mma_kernel<<<dim3(32, 8, 4), 256>>>(out);
}

// round 6
// speedup vs baseline: 2.5153x; 1.5538x over previous
#include <cuda_runtime.h>
#include <cstdint>

// FactorizedTrilinear: B=4, Z=X=C=128, D=V=2 (dv=4), IN=512, R=256
// proj: P_k[b][dv][row][e] = x_k[b,row,dv,:] @ W_k + b_k   (g_P3 pre-rounded to tf32)
// tri:  out[b,z,x,c,dv] = sum_e (p1[z,e]*p2[x,e]) * p3[c,e] via mma.sync tf32,
//       cp.async double-buffered K128 staging, fragments built straight from raw slices.

#define NB  4
#define NZ  128
#define NIN 512
#define NR  256
#define NDV 4

__device__ __align__(16) float g_P1[NB * NDV * NZ * NR];
__device__ __align__(16) float g_P2[NB * NDV * NZ * NR];
__device__ __align__(16) float g_P3[NB * NDV * NZ * NR];

__device__ __forceinline__ uint32_t f2tf32(float f) {
    uint32_t u;
    asm("cvt.rna.tf32.f32 %0, %1;" : "=r"(u) : "f"(f));
    return u;
}
__device__ __forceinline__ void cp16(uint32_t dst, const void* src) {
    asm volatile("cp.async.cg.shared.global [%0], [%1], 16;"
                 :: "r"(dst), "l"(src) : "memory");
}
__device__ __forceinline__ void cp_commit() {
    asm volatile("cp.async.commit_group;" ::: "memory");
}
template <int N>
__device__ __forceinline__ void cp_wait() {
    asm volatile("cp.async.wait_group %0;" :: "n"(N) : "memory");
}

// ---------------------------------------------------------------------------
// Projection: grid (32, 4, 3), 256 threads. Block = 4 z rows, r = tid.
// k==2 (p3) is stored pre-rounded to tf32 (B operand needs no cvt at use).
// ---------------------------------------------------------------------------
__global__ __launch_bounds__(256) void proj_kernel(
    const float* __restrict__ x1, const float* __restrict__ x2, const float* __restrict__ x3,
    const float* __restrict__ W1, const float* __restrict__ bb1,
    const float* __restrict__ W2, const float* __restrict__ bb2,
    const float* __restrict__ W3, const float* __restrict__ bb3)
{
    __shared__ __align__(16) float xs[4 * NIN * NDV];  // [z][e][dv] 32 KB
    __shared__ __align__(16) float ws[16 * NR];        // [e16][r]   16 KB

    const int z0 = blockIdx.x * 4;
    const int b  = blockIdx.y;
    const int k  = blockIdx.z;

    const float* x  = (k == 0) ? x1  : (k == 1) ? x2  : x3;
    const float* W  = (k == 0) ? W1  : (k == 1) ? W2  : W3;
    const float* bs = (k == 0) ? bb1 : (k == 1) ? bb2 : bb3;
    float*       P  = (k == 0) ? g_P1 : (k == 1) ? g_P2 : g_P3;

    const int tid = threadIdx.x;

    const float* xg = x + ((size_t)(b * NZ + z0)) * NDV * NIN;
#pragma unroll
    for (int i = 0; i < 32; i++) {
        int idx = i * 256 + tid;
        int e   = idx & (NIN - 1);
        int zdv = idx >> 9;
        xs[((zdv >> 2) * NIN + e) * NDV + (zdv & 3)] = xg[zdv * NIN + e];
    }

    float acc[4][NDV];
    {
        float bv = bs[tid];
#pragma unroll
        for (int z = 0; z < 4; z++)
#pragma unroll
            for (int dv = 0; dv < NDV; dv++) acc[z][dv] = bv;
    }

    for (int ec = 0; ec < NIN / 16; ec++) {
        __syncthreads();
        const float4* wg = (const float4*)(W + ec * 16 * NR);
        float4* ws4 = (float4*)ws;
#pragma unroll
        for (int i = 0; i < 4; i++) ws4[i * 256 + tid] = wg[i * 256 + tid];
        __syncthreads();

#pragma unroll
        for (int e16 = 0; e16 < 16; e16++) {
            float w = ws[e16 * NR + tid];
            int e = ec * 16 + e16;
#pragma unroll
            for (int z = 0; z < 4; z++) {
                float4 xv = *(const float4*)&xs[(z * NIN + e) * NDV];
                acc[z][0] = fmaf(xv.x, w, acc[z][0]);
                acc[z][1] = fmaf(xv.y, w, acc[z][1]);
                acc[z][2] = fmaf(xv.z, w, acc[z][2]);
                acc[z][3] = fmaf(xv.w, w, acc[z][3]);
            }
        }
    }

#pragma unroll
    for (int z = 0; z < 4; z++)
#pragma unroll
        for (int dv = 0; dv < NDV; dv++) {
            float v = acc[z][dv];
            if (k == 2) v = __uint_as_float(f2tf32(v));
            P[((size_t)((b * NDV + dv) * NZ + z0 + z)) * NR + tid] = v;
        }
}

// ---------------------------------------------------------------------------
// Trilinear. Grid (32, 8, 4): zq x [xq|ch] x b. CTA: M=128(4z x 32x), N=64(c),
// loop dv(4) x K-chunks(2 x 128). 8 warps = 4M x 2N; warp tile M32 x N32
// (2 m-tiles x 4 n-tiles m16n8k8). cp.async double-buffered slice staging.
// ---------------------------------------------------------------------------
#define KC   128
#define KPAD 132
#define OFF_P1 0
#define OFF_P2 (4 * KPAD)                    // 528
#define OFF_P3 (OFF_P2 + 32 * KPAD)          // 4752
#define BUF_F  (OFF_P3 + 64 * KPAD)          // 13200 floats per buffer
#define SMEM_BYTES (2 * BUF_F * 4)           // 105600

__global__ __launch_bounds__(256, 2) void tri_mma_kernel(float* __restrict__ out)
{
    extern __shared__ __align__(16) float sm[];

    const int tid  = threadIdx.x;
    const int wid  = tid >> 5;
    const int lane = tid & 31;
    const int grp  = lane >> 2;
    const int thr4 = lane & 3;

    const int zq = blockIdx.x;
    const int xq = blockIdx.y & 3;
    const int ch = blockIdx.y >> 2;
    const int b  = blockIdx.z;

    const int wm = (wid & 3) * 32;     // warp M offset (covers rows wm..wm+31)
    const int n0 = (wid >> 2) * 32;    // warp N offset
    const int zl = wm >> 5;            // uniform z-row within CTA tile

    const uint32_t smu = (uint32_t)__cvta_generic_to_shared(sm);

    // ---- staging helper (lambda-free, inlined) ----
    // stage s: dv = s>>1, ck = s&1, buffer = s&1
#define STAGE_FILL(s_)                                                          \
    {                                                                           \
        const int dv_ = (s_) >> 1, ck_ = (s_) & 1;                              \
        const uint32_t base = smu + ((s_) & 1) * (BUF_F * 4);                   \
        const float* p1b = g_P1 + ((size_t)((b * NDV + dv_) * NZ + zq * 4)) * NR + ck_ * KC;  \
        const float* p2b = g_P2 + ((size_t)((b * NDV + dv_) * NZ + xq * 32)) * NR + ck_ * KC; \
        const float* p3b = g_P3 + ((size_t)((b * NDV + dv_) * NZ + ch * 64)) * NR + ck_ * KC; \
        if (tid < 128) {                                                        \
            int r = tid >> 5, q = tid & 31;                                     \
            cp16(base + (OFF_P1 + r * KPAD + q * 4) * 4, p1b + r * NR + q * 4); \
        }                                                                       \
        _Pragma("unroll")                                                       \
        for (int i = 0; i < 4; i++) {                                           \
            int g = i * 256 + tid, r = g >> 5, q = g & 31;                      \
            cp16(base + (OFF_P2 + r * KPAD + q * 4) * 4, p2b + r * NR + q * 4); \
        }                                                                       \
        _Pragma("unroll")                                                       \
        for (int i = 0; i < 8; i++) {                                           \
            int g = i * 256 + tid, r = g >> 5, q = g & 31;                      \
            cp16(base + (OFF_P3 + r * KPAD + q * 4) * 4, p3b + r * NR + q * 4); \
        }                                                                       \
    }

    float d[2][4][4];

    STAGE_FILL(0);
    cp_commit();

    for (int s = 0; s < 8; s++) {
        const int dv = s >> 1, ck = s & 1;
        if (s + 1 < 8) {
            STAGE_FILL(s + 1);
            cp_commit();
            cp_wait<1>();
        } else {
            cp_wait<0>();
        }
        __syncthreads();

        if (ck == 0) {
#pragma unroll
            for (int t = 0; t < 2; t++)
#pragma unroll
                for (int j = 0; j < 4; j++)
#pragma unroll
                    for (int i = 0; i < 4; i++) d[t][j][i] = 0.0f;
        }

        const float* p1s = sm + (s & 1) * BUF_F + OFF_P1;
        const float* p2s = sm + (s & 1) * BUF_F + OFF_P2;
        const float* p3s = sm + (s & 1) * BUF_F + OFF_P3;

#pragma unroll 4
        for (int kk = 0; kk < KC / 8; kk++) {
            const int k = kk * 8 + thr4;

            float p1v0 = p1s[zl * KPAD + k];
            float p1v1 = p1s[zl * KPAD + k + 4];

            uint32_t a[2][4];
#pragma unroll
            for (int t = 0; t < 2; t++) {
                const int x0 = 16 * t + grp;
                float v00 = p2s[x0 * KPAD + k];
                float v10 = p2s[(x0 + 8) * KPAD + k];
                float v01 = p2s[x0 * KPAD + k + 4];
                float v11 = p2s[(x0 + 8) * KPAD + k + 4];
                a[t][0] = f2tf32(p1v0 * v00);
                a[t][1] = f2tf32(p1v0 * v10);
                a[t][2] = f2tf32(p1v1 * v01);
                a[t][3] = f2tf32(p1v1 * v11);
            }
            uint32_t bf[4][2];
#pragma unroll
            for (int j = 0; j < 4; j++) {
                const int c = n0 + j * 8 + grp;
                bf[j][0] = __float_as_uint(p3s[c * KPAD + k]);
                bf[j][1] = __float_as_uint(p3s[c * KPAD + k + 4]);
            }
#pragma unroll
            for (int t = 0; t < 2; t++)
#pragma unroll
                for (int j = 0; j < 4; j++)
                    asm volatile(
                        "mma.sync.aligned.m16n8k8.row.col.f32.tf32.tf32.f32 "
                        "{%0,%1,%2,%3}, {%4,%5,%6,%7}, {%8,%9}, {%0,%1,%2,%3};"
                        : "+f"(d[t][j][0]), "+f"(d[t][j][1]),
                          "+f"(d[t][j][2]), "+f"(d[t][j][3])
                        : "r"(a[t][0]), "r"(a[t][1]), "r"(a[t][2]), "r"(a[t][3]),
                          "r"(bf[j][0]), "r"(bf[j][1]));
        }

        if (ck == 1) {
            // Epilogue for this dv.
            const int z0g = zq * 4, x0g = xq * 32;
#pragma unroll
            for (int t = 0; t < 2; t++) {
                const int m0 = wm + 16 * t + grp;        // row0 (m&31 = 16t+grp)
                const int m1 = m0 + 8;
                const size_t rb0 = ((((size_t)(b * NZ + z0g + (m0 >> 5))) * NZ
                                     + x0g + (m0 & 31)) * NZ) * NDV + dv;
                const size_t rb1 = ((((size_t)(b * NZ + z0g + (m1 >> 5))) * NZ
                                     + x0g + (m1 & 31)) * NZ) * NDV + dv;
#pragma unroll
                for (int j = 0; j < 4; j++) {
                    const int cg = ch * 64 + n0 + j * 8 + thr4 * 2;
                    out[rb0 + (size_t)cg * NDV]       = d[t][j][0];
                    out[rb0 + (size_t)(cg + 1) * NDV] = d[t][j][1];
                    out[rb1 + (size_t)cg * NDV]       = d[t][j][2];
                    out[rb1 + (size_t)(cg + 1) * NDV] = d[t][j][3];
                }
            }
        }
        __syncthreads();
    }
#undef STAGE_FILL
}

// ---------------------------------------------------------------------------
extern "C" void kernel_launch(void* const* d_in, const int* in_sizes, int n_in,
                              void* d_out, int out_size)
{
    (void)in_sizes; (void)n_in; (void)out_size;
    const float* x1 = (const float*)d_in[0];
    const float* x2 = (const float*)d_in[1];
    const float* x3 = (const float*)d_in[2];
    const float* W1 = (const float*)d_in[3];
    const float* b1 = (const float*)d_in[4];
    const float* W2 = (const float*)d_in[5];
    const float* b2 = (const float*)d_in[6];
    const float* W3 = (const float*)d_in[7];
    const float* b3 = (const float*)d_in[8];
    float* out = (float*)d_out;

    static int attr_done = 0;
    if (!attr_done) {
        cudaFuncSetAttribute(tri_mma_kernel,
                             cudaFuncAttributeMaxDynamicSharedMemorySize, SMEM_BYTES);
        attr_done = 1;
    }

    proj_kernel<<<dim3(32, NB, 3), 256>>>(x1, x2, x3, W1, b1, W2, b2, W3, b3);
    tri_mma_kernel<<<dim3(32, 8, 4), 256, SMEM_BYTES>>>(out);
}